// round 5
// baseline (speedup 1.0000x reference)
#include <cuda_runtime.h>
#include <cstdint>

#define NN 50000
#define NE 800000
#define CC 128
#define NL 4
#define BN_EPS 1e-5f
#define NC4 (NN * (CC / 4))   // 1,600,000 float4 per [N,C] buffer

// ---------------- scratch (static device globals; no allocation) ----------------
__device__ int   g_is64;                         // 1 if edge_index stored as int64
__device__ __align__(16) int   g_ideg[NN];       // in-degree (excluding self loop)
__device__ __align__(16) float g_dinv[NN];
__device__ __align__(16) int   g_colptr[NN + 1]; // CSR pointers (by destination)
__device__ __align__(16) int   g_cursor[NN];     // fill cursors
__device__ __align__(16) int   g_src[NE];        // CSR: source node per edge
__device__ __align__(16) float g_w[NE];          // CSR: edge weight dinv[r]*dinv[c]
__device__ __align__(16) float g_h[NN * CC];     // GEMM output (messages)
__device__ __align__(16) float g_agg[NN * CC];   // aggregation output
__device__ __align__(16) float g_x[NN * CC];     // layer output / next layer input
__device__ __align__(16) float g_sum[CC];
__device__ __align__(16) float g_sq[CC];
__device__ __align__(16) float g_scale[CC];
__device__ __align__(16) float g_shift[CC];

// ---------------- dtype detection: int32 vs int64 edge_index ----------------
// If stored int64 (little-endian), the high word of every entry (values < 50000)
// is zero. If int32, odd words are random indices — P(all 256 zero) ~ 0.
__global__ void k_detect(const int* __restrict__ ei32) {
    int ornz = 0;
    #pragma unroll 8
    for (int j = 0; j < 256; j++) ornz |= ei32[2 * j + 1];
    g_is64 = (ornz == 0) ? 1 : 0;
}

__device__ __forceinline__ int edge_at(const int* ei32, int is64, long long idx) {
    return is64 ? ei32[2 * idx] : ei32[idx];
}

// ---------------- prolog ----------------
__global__ void k_deg_init() {
    int i = blockIdx.x * blockDim.x + threadIdx.x;
    if (i < NN) g_ideg[i] = 0;
    if (i < CC) { g_sum[i] = 0.f; g_sq[i] = 0.f; }
}

__global__ void k_deg(const int* __restrict__ ei32) {
    int e = blockIdx.x * blockDim.x + threadIdx.x;
    if (e < NE) {
        int c = edge_at(ei32, g_is64, (long long)NE + e);   // col (aggregation target)
        if ((unsigned)c < NN) atomicAdd(&g_ideg[c], 1);
    }
}

__global__ void k_dinv() {
    int i = blockIdx.x * blockDim.x + threadIdx.x;
    if (i < NN) g_dinv[i] = rsqrtf((float)(g_ideg[i] + 1));   // +1 self loop
}

// single-block exclusive scan over 50K degrees -> colptr + cursor
__global__ void k_scan() {
    __shared__ int sh[1024];
    const int tid = threadIdx.x;
    const int per = 49;                    // 1024*49 = 50176 >= NN
    const int base = tid * per;
    int s = 0;
    for (int j = 0; j < per; j++) {
        int idx = base + j;
        if (idx < NN) s += g_ideg[idx];
    }
    sh[tid] = s;
    __syncthreads();
    for (int d = 1; d < 1024; d <<= 1) {
        int v = (tid >= d) ? sh[tid - d] : 0;
        __syncthreads();
        sh[tid] += v;
        __syncthreads();
    }
    int run = (tid > 0) ? sh[tid - 1] : 0;
    for (int j = 0; j < per; j++) {
        int idx = base + j;
        if (idx < NN) {
            g_colptr[idx] = run;
            g_cursor[idx] = run;
            run += g_ideg[idx];
        }
    }
    if (tid == 1023) g_colptr[NN] = sh[1023];
}

__global__ void k_fill(const int* __restrict__ ei32) {
    int e = blockIdx.x * blockDim.x + threadIdx.x;
    if (e < NE) {
        int is64 = g_is64;
        int r = edge_at(ei32, is64, e);
        int c = edge_at(ei32, is64, (long long)NE + e);
        if ((unsigned)r < NN && (unsigned)c < NN) {
            int pos = atomicAdd(&g_cursor[c], 1);
            g_src[pos] = r;
            g_w[pos] = g_dinv[r] * g_dinv[c];
        }
    }
}

// ---------------- GEMM: H = X @ W[l] ----------------
// Block: 64 rows x 128 cols, 256 threads. Static shared: X tile 64x128 (32KB),
// W streamed in 4 chunks of 32x128 (16KB) -> 48KB. Thread tile 8x4.
__global__ void __launch_bounds__(256) k_gemm(const float* __restrict__ Xext,
                                              const float* __restrict__ Wl,
                                              int use_gx)
{
    __shared__ float Xsh[64 * CC];        // 32 KB
    __shared__ float Wsh[32 * CC];        // 16 KB
    const float* X = use_gx ? (const float*)g_x : Xext;
    const int tid = threadIdx.x;
    const int row0 = blockIdx.x * 64;

    {   // load X tile (2048 float4), zero-pad tail rows
        const float4* src = (const float4*)(X + (size_t)row0 * CC);
        float4* dst = (float4*)Xsh;
        int rows = NN - row0; if (rows > 64) rows = 64;
        int n4 = rows * 32;
        #pragma unroll
        for (int i = 0; i < 8; i++) {
            int idx = tid + 256 * i;
            float4 v = make_float4(0.f, 0.f, 0.f, 0.f);
            if (idx < n4) v = src[idx];
            dst[idx] = v;
        }
    }

    const int lane = tid & 31;
    const int warp = tid >> 5;
    float acc[8][4];
    #pragma unroll
    for (int r = 0; r < 8; r++) { acc[r][0] = acc[r][1] = acc[r][2] = acc[r][3] = 0.f; }

    for (int kc = 0; kc < 4; kc++) {
        __syncthreads();
        {   // load W chunk rows [kc*32, kc*32+32): 1024 float4
            const float4* src = (const float4*)(Wl + (size_t)kc * 32 * CC);
            float4* dst = (float4*)Wsh;
            #pragma unroll
            for (int i = 0; i < 4; i++) dst[tid + 256 * i] = src[tid + 256 * i];
        }
        __syncthreads();

        #pragma unroll 4
        for (int kk = 0; kk < 32; kk++) {
            int k = kc * 32 + kk;
            float4 wv = *(const float4*)&Wsh[kk * CC + lane * 4];
            #pragma unroll
            for (int r = 0; r < 8; r++) {
                float xv = Xsh[(warp * 8 + r) * CC + k];
                acc[r][0] = fmaf(xv, wv.x, acc[r][0]);
                acc[r][1] = fmaf(xv, wv.y, acc[r][1]);
                acc[r][2] = fmaf(xv, wv.z, acc[r][2]);
                acc[r][3] = fmaf(xv, wv.w, acc[r][3]);
            }
        }
    }

    #pragma unroll
    for (int r = 0; r < 8; r++) {
        int row = row0 + warp * 8 + r;
        if (row < NN) {
            float4 v = make_float4(acc[r][0], acc[r][1], acc[r][2], acc[r][3]);
            *(float4*)&g_h[(size_t)row * CC + lane * 4] = v;
        }
    }
}

// ---------------- aggregation: CSR gather, one warp per node ----------------
// agg[i] = h[i]*dinv[i]^2 + sum_{e in in(i)} h[src[e]] * w[e].  No atomics.
// 4x unrolled edge loop: 4 independent LDG.128 in flight to cover L2 latency.
__global__ void __launch_bounds__(256) k_aggregate()
{
    int i = (blockIdx.x * blockDim.x + threadIdx.x) >> 5;
    int lane = threadIdx.x & 31;
    if (i >= NN) return;

    float di = __ldg(&g_dinv[i]);
    float s2 = di * di;
    float4 v = __ldg((const float4*)(g_h + (size_t)i * CC) + lane);
    float4 acc = make_float4(v.x * s2, v.y * s2, v.z * s2, v.w * s2);

    int e0 = __ldg(&g_colptr[i]);
    int e1 = __ldg(&g_colptr[i + 1]);

    int e = e0;
    for (; e + 3 < e1; e += 4) {
        int   sA = __ldg(&g_src[e]);
        int   sB = __ldg(&g_src[e + 1]);
        int   sC = __ldg(&g_src[e + 2]);
        int   sD = __ldg(&g_src[e + 3]);
        float wA = __ldg(&g_w[e]);
        float wB = __ldg(&g_w[e + 1]);
        float wC = __ldg(&g_w[e + 2]);
        float wD = __ldg(&g_w[e + 3]);
        float4 uA = __ldg((const float4*)(g_h + (size_t)sA * CC) + lane);
        float4 uB = __ldg((const float4*)(g_h + (size_t)sB * CC) + lane);
        float4 uC = __ldg((const float4*)(g_h + (size_t)sC * CC) + lane);
        float4 uD = __ldg((const float4*)(g_h + (size_t)sD * CC) + lane);
        acc.x = fmaf(uA.x, wA, acc.x); acc.y = fmaf(uA.y, wA, acc.y);
        acc.z = fmaf(uA.z, wA, acc.z); acc.w = fmaf(uA.w, wA, acc.w);
        acc.x = fmaf(uB.x, wB, acc.x); acc.y = fmaf(uB.y, wB, acc.y);
        acc.z = fmaf(uB.z, wB, acc.z); acc.w = fmaf(uB.w, wB, acc.w);
        acc.x = fmaf(uC.x, wC, acc.x); acc.y = fmaf(uC.y, wC, acc.y);
        acc.z = fmaf(uC.z, wC, acc.z); acc.w = fmaf(uC.w, wC, acc.w);
        acc.x = fmaf(uD.x, wD, acc.x); acc.y = fmaf(uD.y, wD, acc.y);
        acc.z = fmaf(uD.z, wD, acc.z); acc.w = fmaf(uD.w, wD, acc.w);
    }
    for (; e < e1; e++) {
        int   s = __ldg(&g_src[e]);
        float wgt = __ldg(&g_w[e]);
        float4 u = __ldg((const float4*)(g_h + (size_t)s * CC) + lane);
        acc.x = fmaf(u.x, wgt, acc.x); acc.y = fmaf(u.y, wgt, acc.y);
        acc.z = fmaf(u.z, wgt, acc.z); acc.w = fmaf(u.w, wgt, acc.w);
    }

    *((float4*)(g_agg + (size_t)i * CC) + lane) = acc;
}

// ---------------- BN stats: per-channel sum & sumsq (scalar atomics only) ----------------
__global__ void __launch_bounds__(256) k_stats()
{
    __shared__ float ssum[CC], ssq[CC];
    const int tid = threadIdx.x;
    if (tid < CC) { ssum[tid] = 0.f; ssq[tid] = 0.f; }
    __syncthreads();

    const int stride = gridDim.x * 256;
    float s0 = 0, s1 = 0, s2 = 0, s3 = 0;
    float q0 = 0, q1 = 0, q2 = 0, q3 = 0;
    const float4* A = (const float4*)g_agg;
    for (int f = blockIdx.x * 256 + tid; f < NC4; f += stride) {
        float4 v = __ldg(&A[f]);
        s0 += v.x; s1 += v.y; s2 += v.z; s3 += v.w;
        q0 += v.x * v.x; q1 += v.y * v.y; q2 += v.z * v.z; q3 += v.w * v.w;
    }
    int ch = (tid & 31) * 4;
    atomicAdd(&ssum[ch + 0], s0); atomicAdd(&ssum[ch + 1], s1);
    atomicAdd(&ssum[ch + 2], s2); atomicAdd(&ssum[ch + 3], s3);
    atomicAdd(&ssq[ch + 0], q0);  atomicAdd(&ssq[ch + 1], q1);
    atomicAdd(&ssq[ch + 2], q2);  atomicAdd(&ssq[ch + 3], q3);
    __syncthreads();
    if (tid < CC) {
        atomicAdd(&g_sum[tid], ssum[tid]);
        atomicAdd(&g_sq[tid], ssq[tid]);
    }
}

// ---------------- finalize BN params (bias b cancels inside BN) ----------------
__global__ void k_finalize(const float* __restrict__ gamma, const float* __restrict__ beta)
{
    int c = threadIdx.x;   // 128 threads, 1 block
    float mu = g_sum[c] * (1.0f / NN);
    float var = g_sq[c] * (1.0f / NN) - mu * mu;
    float rstd = rsqrtf(var + BN_EPS);
    float sc = rstd * gamma[c];
    g_scale[c] = sc;
    g_shift[c] = beta[c] - mu * sc;
    g_sum[c] = 0.f; g_sq[c] = 0.f;   // pre-zero for next layer
}

// ---------------- normalize + relu ----------------
__global__ void __launch_bounds__(256) k_norm_relu(float* __restrict__ OUT, int to_gx)
{
    __shared__ float4 ssc[32], ssh[32];
    const int tid = threadIdx.x;
    if (tid < 32) {
        ssc[tid] = ((const float4*)g_scale)[tid];
        ssh[tid] = ((const float4*)g_shift)[tid];
    }
    __syncthreads();
    const int stride = gridDim.x * 256;
    const float4* A = (const float4*)g_agg;
    float4* O = to_gx ? (float4*)g_x : (float4*)OUT;
    for (int f = blockIdx.x * 256 + tid; f < NC4; f += stride) {
        int ch = f & 31;
        float4 v = A[f];
        float4 sc = ssc[ch];
        float4 sh = ssh[ch];
        float4 o;
        o.x = fmaxf(fmaf(v.x, sc.x, sh.x), 0.f);
        o.y = fmaxf(fmaf(v.y, sc.y, sh.y), 0.f);
        o.z = fmaxf(fmaf(v.z, sc.z, sh.z), 0.f);
        o.w = fmaxf(fmaf(v.w, sc.w, sh.w), 0.f);
        O[f] = o;
    }
}

// ---------------- launch ----------------
extern "C" void kernel_launch(void* const* d_in, const int* in_sizes, int n_in,
                              void* d_out, int out_size)
{
    const float* x     = (const float*)d_in[0];
    const int*   ei32  = (const int*)d_in[1];      // int32 on disk (JAX x64 disabled); detector handles int64 too
    const float* W     = (const float*)d_in[2];
    /* d_in[3] = b: algebraically cancels inside BatchNorm -> unused */
    const float* gamma = (const float*)d_in[4];
    const float* beta  = (const float*)d_in[5];
    float*       out   = (float*)d_out;

    // prolog: build normalized CSR once (edge structure shared by all layers)
    k_detect<<<1, 1>>>(ei32);
    k_deg_init<<<(NN + 255) / 256, 256>>>();
    k_deg<<<(NE + 255) / 256, 256>>>(ei32);
    k_dinv<<<(NN + 255) / 256, 256>>>();
    k_scan<<<1, 1024>>>();
    k_fill<<<(NE + 255) / 256, 256>>>(ei32);

    const int GEMM_BLOCKS = (NN + 63) / 64;            // 782
    const int AGG_BLOCKS  = (NN * 32 + 255) / 256;     // 6250 (one warp per node)
    const int EW_BLOCKS   = 1184;

    for (int l = 0; l < NL; l++) {
        int use_gx = (l != 0);
        int to_gx  = (l != NL - 1);
        k_gemm<<<GEMM_BLOCKS, 256>>>(x, W + (size_t)l * CC * CC, use_gx);
        k_aggregate<<<AGG_BLOCKS, 256>>>();
        k_stats<<<EW_BLOCKS, 256>>>();
        k_finalize<<<1, CC>>>(gamma + l * CC, beta + l * CC);
        k_norm_relu<<<EW_BLOCKS, 256>>>(out, to_gx);
    }
    (void)in_sizes; (void)n_in; (void)out_size;
}

// round 9
// speedup vs baseline: 1.0870x; 1.0870x over previous
#include <cuda_runtime.h>
#include <cstdint>

#define NN 50000
#define NE 800000
#define CC 128
#define NL 4
#define BN_EPS 1e-5f
#define NC4 (NN * (CC / 4))   // 1,600,000 float4 per [N,C] buffer

// ---------------- scratch (static device globals; no allocation) ----------------
__device__ int   g_is64;                         // 1 if edge_index stored as int64
__device__ __align__(16) int   g_ideg[NN];       // in-degree (excluding self loop)
__device__ __align__(16) float g_dinv[NN];
__device__ __align__(16) int   g_colptr[NN + 1]; // CSR pointers (by destination)
__device__ __align__(16) int   g_cursor[NN];     // fill cursors
__device__ __align__(16) int   g_src[NE];        // CSR: source node per edge
__device__ __align__(16) float g_w[NE];          // CSR: edge weight dinv[r]*dinv[c]
__device__ __align__(16) float g_h[NN * CC];     // GEMM output (messages)
__device__ __align__(16) float g_agg[NN * CC];   // aggregation output
__device__ __align__(16) float g_sum[CC];
__device__ __align__(16) float g_sq[CC];
__device__ __align__(16) float g_scale[CC];
__device__ __align__(16) float g_shift[CC];

// ---------------- dtype detection: int32 vs int64 edge_index ----------------
__global__ void k_detect(const int* __restrict__ ei32) {
    int ornz = 0;
    #pragma unroll 8
    for (int j = 0; j < 256; j++) ornz |= ei32[2 * j + 1];
    g_is64 = (ornz == 0) ? 1 : 0;
}

__device__ __forceinline__ int edge_at(const int* ei32, int is64, long long idx) {
    return is64 ? ei32[2 * idx] : ei32[idx];
}

// ---------------- prolog ----------------
__global__ void k_deg_init() {
    int i = blockIdx.x * blockDim.x + threadIdx.x;
    if (i < NN) g_ideg[i] = 0;
    if (i < CC) { g_sum[i] = 0.f; g_sq[i] = 0.f; }
}

__global__ void k_deg(const int* __restrict__ ei32) {
    int e = blockIdx.x * blockDim.x + threadIdx.x;
    if (e < NE) {
        int c = edge_at(ei32, g_is64, (long long)NE + e);
        if ((unsigned)c < NN) atomicAdd(&g_ideg[c], 1);
    }
}

__global__ void k_dinv() {
    int i = blockIdx.x * blockDim.x + threadIdx.x;
    if (i < NN) g_dinv[i] = rsqrtf((float)(g_ideg[i] + 1));   // +1 self loop
}

// single-block exclusive scan over 50K degrees -> colptr + cursor
__global__ void k_scan() {
    __shared__ int sh[1024];
    const int tid = threadIdx.x;
    const int per = 49;                    // 1024*49 >= NN
    const int base = tid * per;
    int s = 0;
    for (int j = 0; j < per; j++) {
        int idx = base + j;
        if (idx < NN) s += g_ideg[idx];
    }
    sh[tid] = s;
    __syncthreads();
    for (int d = 1; d < 1024; d <<= 1) {
        int v = (tid >= d) ? sh[tid - d] : 0;
        __syncthreads();
        sh[tid] += v;
        __syncthreads();
    }
    int run = (tid > 0) ? sh[tid - 1] : 0;
    for (int j = 0; j < per; j++) {
        int idx = base + j;
        if (idx < NN) {
            g_colptr[idx] = run;
            g_cursor[idx] = run;
            run += g_ideg[idx];
        }
    }
    if (tid == 1023) g_colptr[NN] = sh[1023];
}

__global__ void k_fill(const int* __restrict__ ei32) {
    int e = blockIdx.x * blockDim.x + threadIdx.x;
    if (e < NE) {
        int is64 = g_is64;
        int r = edge_at(ei32, is64, e);
        int c = edge_at(ei32, is64, (long long)NE + e);
        if ((unsigned)r < NN && (unsigned)c < NN) {
            int pos = atomicAdd(&g_cursor[c], 1);
            g_src[pos] = r;
            g_w[pos] = g_dinv[r] * g_dinv[c];
        }
    }
}

// ---------------- GEMM: H = X @ W[l], with fused BN+ReLU on the input ----------------
// fused=0: X = external input. fused=1: X = relu(g_agg * scale + shift) applied
// on the fly during the SMEM tile load (eliminates the standalone norm pass).
// SMEM budget trick: the scale/shift staging (1KB) aliases the FIRST 1KB of Wsh;
// it is consumed during the X-tile fill, and Wsh is only written after the
// __syncthreads() that opens the kc loop -> lifetimes disjoint, total 48KB exact.
__global__ void __launch_bounds__(256) k_gemm(const float* __restrict__ Xext,
                                              const float* __restrict__ Wl,
                                              int fused)
{
    __shared__ float Xsh[64 * CC];        // 32 KB
    __shared__ float Wsh[32 * CC];        // 16 KB (first 1KB doubles as scale/shift staging)
    float4* ssc = (float4*)Wsh;           // 32 float4 = 512 B
    float4* ssh = (float4*)(Wsh + 128);   // 32 float4 = 512 B
    const int tid = threadIdx.x;
    const int row0 = blockIdx.x * 64;

    if (fused) {
        if (tid < 32) {
            ssc[tid] = ((const float4*)g_scale)[tid];
            ssh[tid] = ((const float4*)g_shift)[tid];
        }
        __syncthreads();
    }

    {   // load X tile (2048 float4), zero-pad tail rows, fused affine+relu
        const float4* src = fused ? ((const float4*)g_agg + (size_t)row0 * 32)
                                  : ((const float4*)(Xext + (size_t)row0 * CC));
        float4* dst = (float4*)Xsh;
        int rows = NN - row0; if (rows > 64) rows = 64;
        int n4 = rows * 32;
        #pragma unroll
        for (int i = 0; i < 8; i++) {
            int idx = tid + 256 * i;
            float4 v = make_float4(0.f, 0.f, 0.f, 0.f);
            if (idx < n4) v = src[idx];
            if (fused) {
                int ch = idx & 31;
                float4 sc = ssc[ch];
                float4 sh = ssh[ch];
                v.x = fmaxf(fmaf(v.x, sc.x, sh.x), 0.f);
                v.y = fmaxf(fmaf(v.y, sc.y, sh.y), 0.f);
                v.z = fmaxf(fmaf(v.z, sc.z, sh.z), 0.f);
                v.w = fmaxf(fmaf(v.w, sc.w, sh.w), 0.f);
            }
            dst[idx] = v;
        }
    }

    const int lane = tid & 31;
    const int warp = tid >> 5;
    float acc[8][4];
    #pragma unroll
    for (int r = 0; r < 8; r++) { acc[r][0] = acc[r][1] = acc[r][2] = acc[r][3] = 0.f; }

    for (int kc = 0; kc < 4; kc++) {
        __syncthreads();   // also retires ssc/ssh reads before Wsh overwrite
        {   // load W chunk rows [kc*32, kc*32+32): 1024 float4
            const float4* src = (const float4*)(Wl + (size_t)kc * 32 * CC);
            float4* dst = (float4*)Wsh;
            #pragma unroll
            for (int i = 0; i < 4; i++) dst[tid + 256 * i] = src[tid + 256 * i];
        }
        __syncthreads();

        #pragma unroll 4
        for (int kk = 0; kk < 32; kk++) {
            int k = kc * 32 + kk;
            float4 wv = *(const float4*)&Wsh[kk * CC + lane * 4];
            #pragma unroll
            for (int r = 0; r < 8; r++) {
                float xv = Xsh[(warp * 8 + r) * CC + k];
                acc[r][0] = fmaf(xv, wv.x, acc[r][0]);
                acc[r][1] = fmaf(xv, wv.y, acc[r][1]);
                acc[r][2] = fmaf(xv, wv.z, acc[r][2]);
                acc[r][3] = fmaf(xv, wv.w, acc[r][3]);
            }
        }
    }

    #pragma unroll
    for (int r = 0; r < 8; r++) {
        int row = row0 + warp * 8 + r;
        if (row < NN) {
            float4 v = make_float4(acc[r][0], acc[r][1], acc[r][2], acc[r][3]);
            *(float4*)&g_h[(size_t)row * CC + lane * 4] = v;
        }
    }
}

// ---------------- aggregation + fused BN stats ----------------
// Grid-stride over nodes, one warp per node. Each lane owns channels
// [4*lane, 4*lane+4): stats accumulate in registers across the warp's nodes,
// flushed once per block via shared + global atomics.
__global__ void __launch_bounds__(256) k_aggregate()
{
    __shared__ float ssum[CC], ssq[CC];
    const int tid = threadIdx.x;
    if (tid < CC) { ssum[tid] = 0.f; ssq[tid] = 0.f; }
    __syncthreads();

    const int gw = (blockIdx.x * 256 + tid) >> 5;
    const int lane = tid & 31;
    const int nw = (gridDim.x * 256) >> 5;

    float s0 = 0, s1 = 0, s2 = 0, s3 = 0;
    float q0 = 0, q1 = 0, q2 = 0, q3 = 0;

    for (int i = gw; i < NN; i += nw) {
        float di = __ldg(&g_dinv[i]);
        float s2i = di * di;
        float4 v = __ldg((const float4*)(g_h + (size_t)i * CC) + lane);
        float4 acc = make_float4(v.x * s2i, v.y * s2i, v.z * s2i, v.w * s2i);

        int e0 = __ldg(&g_colptr[i]);
        int e1 = __ldg(&g_colptr[i + 1]);

        int e = e0;
        for (; e + 3 < e1; e += 4) {
            int   sA = __ldg(&g_src[e]);
            int   sB = __ldg(&g_src[e + 1]);
            int   sC = __ldg(&g_src[e + 2]);
            int   sD = __ldg(&g_src[e + 3]);
            float wA = __ldg(&g_w[e]);
            float wB = __ldg(&g_w[e + 1]);
            float wC = __ldg(&g_w[e + 2]);
            float wD = __ldg(&g_w[e + 3]);
            float4 uA = __ldg((const float4*)(g_h + (size_t)sA * CC) + lane);
            float4 uB = __ldg((const float4*)(g_h + (size_t)sB * CC) + lane);
            float4 uC = __ldg((const float4*)(g_h + (size_t)sC * CC) + lane);
            float4 uD = __ldg((const float4*)(g_h + (size_t)sD * CC) + lane);
            acc.x = fmaf(uA.x, wA, acc.x); acc.y = fmaf(uA.y, wA, acc.y);
            acc.z = fmaf(uA.z, wA, acc.z); acc.w = fmaf(uA.w, wA, acc.w);
            acc.x = fmaf(uB.x, wB, acc.x); acc.y = fmaf(uB.y, wB, acc.y);
            acc.z = fmaf(uB.z, wB, acc.z); acc.w = fmaf(uB.w, wB, acc.w);
            acc.x = fmaf(uC.x, wC, acc.x); acc.y = fmaf(uC.y, wC, acc.y);
            acc.z = fmaf(uC.z, wC, acc.z); acc.w = fmaf(uC.w, wC, acc.w);
            acc.x = fmaf(uD.x, wD, acc.x); acc.y = fmaf(uD.y, wD, acc.y);
            acc.z = fmaf(uD.z, wD, acc.z); acc.w = fmaf(uD.w, wD, acc.w);
        }
        for (; e < e1; e++) {
            int   s = __ldg(&g_src[e]);
            float wgt = __ldg(&g_w[e]);
            float4 u = __ldg((const float4*)(g_h + (size_t)s * CC) + lane);
            acc.x = fmaf(u.x, wgt, acc.x); acc.y = fmaf(u.y, wgt, acc.y);
            acc.z = fmaf(u.z, wgt, acc.z); acc.w = fmaf(u.w, wgt, acc.w);
        }

        *((float4*)(g_agg + (size_t)i * CC) + lane) = acc;

        s0 += acc.x; s1 += acc.y; s2 += acc.z; s3 += acc.w;
        q0 += acc.x * acc.x; q1 += acc.y * acc.y;
        q2 += acc.z * acc.z; q3 += acc.w * acc.w;
    }

    int ch = lane * 4;
    atomicAdd(&ssum[ch + 0], s0); atomicAdd(&ssum[ch + 1], s1);
    atomicAdd(&ssum[ch + 2], s2); atomicAdd(&ssum[ch + 3], s3);
    atomicAdd(&ssq[ch + 0], q0);  atomicAdd(&ssq[ch + 1], q1);
    atomicAdd(&ssq[ch + 2], q2);  atomicAdd(&ssq[ch + 3], q3);
    __syncthreads();
    if (tid < CC) {
        atomicAdd(&g_sum[tid], ssum[tid]);
        atomicAdd(&g_sq[tid], ssq[tid]);
    }
}

// ---------------- finalize BN params (bias b cancels inside BN) ----------------
__global__ void k_finalize(const float* __restrict__ gamma, const float* __restrict__ beta)
{
    int c = threadIdx.x;   // 128 threads, 1 block
    float mu = g_sum[c] * (1.0f / NN);
    float var = g_sq[c] * (1.0f / NN) - mu * mu;
    float rstd = rsqrtf(var + BN_EPS);
    float sc = rstd * gamma[c];
    g_scale[c] = sc;
    g_shift[c] = beta[c] - mu * sc;
    g_sum[c] = 0.f; g_sq[c] = 0.f;   // pre-zero for next layer
}

// ---------------- final normalize + relu -> out (last layer only) ----------------
__global__ void __launch_bounds__(256) k_norm_relu(float* __restrict__ OUT)
{
    __shared__ float4 ssc[32], ssh[32];
    const int tid = threadIdx.x;
    if (tid < 32) {
        ssc[tid] = ((const float4*)g_scale)[tid];
        ssh[tid] = ((const float4*)g_shift)[tid];
    }
    __syncthreads();
    const int stride = gridDim.x * 256;
    const float4* A = (const float4*)g_agg;
    float4* O = (float4*)OUT;
    for (int f = blockIdx.x * 256 + tid; f < NC4; f += stride) {
        int ch = f & 31;
        float4 v = A[f];
        float4 sc = ssc[ch];
        float4 sh = ssh[ch];
        float4 o;
        o.x = fmaxf(fmaf(v.x, sc.x, sh.x), 0.f);
        o.y = fmaxf(fmaf(v.y, sc.y, sh.y), 0.f);
        o.z = fmaxf(fmaf(v.z, sc.z, sh.z), 0.f);
        o.w = fmaxf(fmaf(v.w, sc.w, sh.w), 0.f);
        O[f] = o;
    }
}

// ---------------- launch ----------------
extern "C" void kernel_launch(void* const* d_in, const int* in_sizes, int n_in,
                              void* d_out, int out_size)
{
    const float* x     = (const float*)d_in[0];
    const int*   ei32  = (const int*)d_in[1];      // int32 on disk (JAX x64 disabled); detector handles int64 too
    const float* W     = (const float*)d_in[2];
    /* d_in[3] = b: algebraically cancels inside BatchNorm -> unused */
    const float* gamma = (const float*)d_in[4];
    const float* beta  = (const float*)d_in[5];
    float*       out   = (float*)d_out;

    // prolog: build normalized CSR once (edge structure shared by all layers)
    k_detect<<<1, 1>>>(ei32);
    k_deg_init<<<(NN + 255) / 256, 256>>>();
    k_deg<<<(NE + 255) / 256, 256>>>(ei32);
    k_dinv<<<(NN + 255) / 256, 256>>>();
    k_scan<<<1, 1024>>>();
    k_fill<<<(NE + 255) / 256, 256>>>(ei32);

    const int GEMM_BLOCKS = (NN + 63) / 64;   // 782
    const int AGG_BLOCKS  = 1184;             // 8 blocks/SM, grid-stride over nodes
    const int EW_BLOCKS   = 1184;

    for (int l = 0; l < NL; l++) {
        k_gemm<<<GEMM_BLOCKS, 256>>>(x, W + (size_t)l * CC * CC, (l != 0));
        k_aggregate<<<AGG_BLOCKS, 256>>>();
        k_finalize<<<1, CC>>>(gamma + l * CC, beta + l * CC);
    }
    k_norm_relu<<<EW_BLOCKS, 256>>>(out);
    (void)in_sizes; (void)n_in; (void)out_size;
}